// round 12
// baseline (speedup 1.0000x reference)
#include <cuda_runtime.h>
#include <cuda_bf16.h>
#include <cuda_fp16.h>
#include <cstdint>

// Problem constants
#define MAXN 50000
#define MAXE 800000
#define IN_DIM 128
#define HD 128
#define ASTRIDE 136               // fp16 elems per smem row (272B, conflict-free ldmatrix)
#define IMG_BYTES (128 * ASTRIDE * 2)           // 34816 B per image
#define QKV_SMEM (3 * IMG_BYTES)                // Ahi, Alo, B = 104448 B -> 2 blocks/SM

// ---- scratch (static device arrays; no allocation allowed) ----
__device__ float  g_Q[(size_t)MAXN * HD];      // pre-scaled by 0.25, fp32
__device__ __half g_KVh[(size_t)MAXN * 256];   // per node: [0:128)=K, [128:256)=V (fp16)
__device__ int    g_deg[MAXN];
__device__ int    g_off[MAXN];                 // after scatter: g_off[d] = segment END of d
__device__ int    g_src_sorted[MAXE];
// W^T fp16 padded images: [matrix][n=128 rows][ASTRIDE k-cols]
__device__ __half g_Bimg[3][128 * ASTRIDE];

__device__ __forceinline__ uint32_t smem_u32(const void* p) {
    uint32_t a;
    asm("{ .reg .u64 t; cvta.to.shared.u64 t, %1; cvt.u32.u64 %0, t; }" : "=r"(a) : "l"(p));
    return a;
}

#define LDSM_X4(r0, r1, r2, r3, addr)                                            \
    asm volatile("ldmatrix.sync.aligned.m8n8.x4.shared.b16 {%0,%1,%2,%3}, [%4];" \
                 : "=r"(r0), "=r"(r1), "=r"(r2), "=r"(r3) : "r"(addr))

#define MMA16816F(c, a0, a1, a2, a3, b0, b1)                                     \
    asm volatile("mma.sync.aligned.m16n8k16.row.col.f32.f16.f16.f32 "            \
                 "{%0,%1,%2,%3}, {%4,%5,%6,%7}, {%8,%9}, {%0,%1,%2,%3};"         \
                 : "+f"((c)[0]), "+f"((c)[1]), "+f"((c)[2]), "+f"((c)[3])        \
                 : "r"(a0), "r"(a1), "r"(a2), "r"(a3), "r"(b0), "r"(b1))

// ---------------------------------------------------------------------------
// Prepass: W^T fp16 padded images. B[n][k] = W[k][n].
// ---------------------------------------------------------------------------
__global__ void wprep_kernel(const float* __restrict__ Wq,
                             const float* __restrict__ Wk,
                             const float* __restrict__ Wv)
{
    int idx = blockIdx.x * blockDim.x + threadIdx.x;
    if (idx >= 3 * 128 * 128) return;
    int m = idx >> 14, rem = idx & 16383, n = rem >> 7, k = rem & 127;
    const float* W = (m == 0) ? Wq : ((m == 1) ? Wk : Wv);
    g_Bimg[m][n * ASTRIDE + k] = __float2half_rn(W[k * 128 + n]);
}

// ---------------------------------------------------------------------------
// Kernel 1: QKV projection via mma.sync fp16 2-product split-GEMM.
// grid = (ceil(N/128), 3); blockIdx.y = m selects {Q,K,V} -> each block does
// ONE matrix: stage A (hi/lo) + one B image + one compute pass + epilogue.
// 3x blocks, 1/3 chain length per block -> staging/sync latency hidden by
// co-resident blocks. A = Ahi + Alo (fp16 hi + residual); B = fp16(W^T).
// ---------------------------------------------------------------------------
__global__ void __launch_bounds__(256, 2) qkv_mma_kernel(
    const float* __restrict__ h,
    const float* __restrict__ bq, const float* __restrict__ bk, const float* __restrict__ bv,
    int N)
{
    extern __shared__ __half smem[];
    __half* Ahi = smem;                      // [row][k]
    __half* Alo = smem + 128 * ASTRIDE;
    __half* Bs  = smem + 2 * 128 * ASTRIDE;  // [n][k]

    const int tid = threadIdx.x;
    const int lane = tid & 31, warp = tid >> 5;
    const int wm = warp & 3;       // m-chunk: rows [32*wm, 32*wm+32)
    const int wn = warp >> 2;      // n-chunk: cols [64*wn, 64*wn+64)
    const int node0 = blockIdx.x * 128;
    const int m = blockIdx.y;      // 0=Q, 1=K, 2=V

    // ---- Stage B: fp16 image copy (35 KB, coalesced float4) ----
    {
        const float4* sb = reinterpret_cast<const float4*>(g_Bimg[m]);
        float4* db = reinterpret_cast<float4*>(Bs);
        for (int i = tid; i < IMG_BYTES / 16; i += 256) db[i] = sb[i];
    }

    // ---- Stage A: fp32 -> fp16 hi + residual. Thread t: row t>>1, col-half t&1. ----
    {
        const int r = tid >> 1, cb = (tid & 1) * 64;
        const bool valid = (node0 + r) < N;
        const float* hp = h + (size_t)(node0 + r) * IN_DIM + cb;
        __half* ah = Ahi + r * ASTRIDE + cb;
        __half* al = Alo + r * ASTRIDE + cb;
#pragma unroll
        for (int i = 0; i < 64; i += 4) {
            float4 v = valid ? *reinterpret_cast<const float4*>(hp + i)
                             : make_float4(0.f, 0.f, 0.f, 0.f);
            __half hx = __float2half_rn(v.x), hy = __float2half_rn(v.y);
            __half hz = __float2half_rn(v.z), hw = __float2half_rn(v.w);
            __half lx = __float2half_rn(v.x - __half2float(hx));
            __half ly = __float2half_rn(v.y - __half2float(hy));
            __half lz = __float2half_rn(v.z - __half2float(hz));
            __half lw = __float2half_rn(v.w - __half2float(hw));
            *reinterpret_cast<__half2*>(ah + i)     = __halves2half2(hx, hy);
            *reinterpret_cast<__half2*>(ah + i + 2) = __halves2half2(hz, hw);
            *reinterpret_cast<__half2*>(al + i)     = __halves2half2(lx, ly);
            *reinterpret_cast<__half2*>(al + i + 2) = __halves2half2(lz, lw);
        }
    }
    __syncthreads();

    const uint32_t uAhi = smem_u32(Ahi), uAlo = smem_u32(Alo);
    const uint32_t uBs  = smem_u32(Bs);

    // A: row = wm*32 + mt*16 + (lane&15); byte += (lane>>4)*16 + kk*32
    const uint32_t aRow = (uint32_t)(wm * 32 + (lane & 15)) * 272u + (uint32_t)(lane >> 4) * 16u;
    // B: n-row = wn*64 + p*16 + ((lane>>4)&1)*8 + (lane&7); byte += ((lane>>3)&1)*16 + kk*32
    const uint32_t bRow = (uint32_t)(wn * 64 + ((lane >> 4) & 1) * 8 + (lane & 7)) * 272u
                        + (uint32_t)((lane >> 3) & 1) * 16u;

    float acc[2][8][4];
#pragma unroll
    for (int mt = 0; mt < 2; mt++)
#pragma unroll
        for (int nt = 0; nt < 8; nt++)
#pragma unroll
            for (int c = 0; c < 4; c++) acc[mt][nt][c] = 0.f;

#pragma unroll
    for (int kk = 0; kk < 8; kk++) {
        const uint32_t kO = (uint32_t)kk * 32u;

        uint32_t ah[2][4], al[2][4];
#pragma unroll
        for (int mt = 0; mt < 2; mt++) {
            const uint32_t ro = aRow + (uint32_t)(mt * 16) * 272u + kO;
            LDSM_X4(ah[mt][0], ah[mt][1], ah[mt][2], ah[mt][3], uAhi + ro);
            LDSM_X4(al[mt][0], al[mt][1], al[mt][2], al[mt][3], uAlo + ro);
        }

        uint32_t bf[8][2];
#pragma unroll
        for (int p = 0; p < 4; p++) {
            const uint32_t ro = bRow + (uint32_t)(p * 16) * 272u + kO;
            LDSM_X4(bf[2 * p][0], bf[2 * p][1], bf[2 * p + 1][0], bf[2 * p + 1][1], uBs + ro);
        }

#pragma unroll
        for (int mt = 0; mt < 2; mt++)
#pragma unroll
            for (int nt = 0; nt < 8; nt++) {
                MMA16816F(acc[mt][nt], ah[mt][0], ah[mt][1], ah[mt][2], ah[mt][3],
                          bf[nt][0], bf[nt][1]);
                MMA16816F(acc[mt][nt], al[mt][0], al[mt][1], al[mt][2], al[mt][3],
                          bf[nt][0], bf[nt][1]);
            }
    }

    // ---- Epilogue ----
    const float* bb = (m == 0) ? bq : ((m == 1) ? bk : bv);
#pragma unroll
    for (int mt = 0; mt < 2; mt++) {
        const int r0 = node0 + wm * 32 + mt * 16 + (lane >> 2);
#pragma unroll
        for (int nt = 0; nt < 8; nt++) {
            const int col = wn * 64 + nt * 8 + (lane & 3) * 2;
            const float b0 = __ldg(bb + col), b1 = __ldg(bb + col + 1);
            if (m == 0) {
                if (r0 < N) {
                    float2 o = make_float2((acc[mt][nt][0] + b0) * 0.25f,
                                           (acc[mt][nt][1] + b1) * 0.25f);
                    *reinterpret_cast<float2*>(g_Q + (size_t)r0 * HD + col) = o;
                }
                if (r0 + 8 < N) {
                    float2 o = make_float2((acc[mt][nt][2] + b0) * 0.25f,
                                           (acc[mt][nt][3] + b1) * 0.25f);
                    *reinterpret_cast<float2*>(g_Q + (size_t)(r0 + 8) * HD + col) = o;
                }
            } else {
                const int voff = (m == 2) ? 128 : 0;   // K at +0, V at +128
                if (r0 < N) {
                    __half2 o = __floats2half2_rn(acc[mt][nt][0] + b0,
                                                  acc[mt][nt][1] + b1);
                    *reinterpret_cast<__half2*>(g_KVh + (size_t)r0 * 256 + voff + col) = o;
                }
                if (r0 + 8 < N) {
                    __half2 o = __floats2half2_rn(acc[mt][nt][2] + b0,
                                                  acc[mt][nt][3] + b1);
                    *reinterpret_cast<__half2*>(g_KVh + (size_t)(r0 + 8) * 256 + voff + col) = o;
                }
            }
        }
    }
}

// ---------------------------------------------------------------------------
// CSR build: hist -> single-block scan -> scatter (atomic bump on g_off)
// ---------------------------------------------------------------------------
__global__ void hist_kernel(const int* __restrict__ dst, int E)
{
    int i = blockIdx.x * blockDim.x + threadIdx.x;
    if (i < E) atomicAdd(&g_deg[dst[i]], 1);
}

__global__ __launch_bounds__(1024) void scan_kernel(int N)
{
    __shared__ int warp_sums[32];
    __shared__ int s_carry;
    const int t = threadIdx.x;
    const int lane = t & 31, wid = t >> 5;
    if (t == 0) s_carry = 0;
    __syncthreads();

    for (int base = 0; base < N; base += 1024) {
        int i = base + t;
        int x = (i < N) ? g_deg[i] : 0;
        int inc = x;
#pragma unroll
        for (int d = 1; d < 32; d <<= 1) {
            int v = __shfl_up_sync(0xffffffffu, inc, d);
            if (lane >= d) inc += v;
        }
        if (lane == 31) warp_sums[wid] = inc;
        __syncthreads();
        if (wid == 0) {
            int ws = warp_sums[lane];
#pragma unroll
            for (int d = 1; d < 32; d <<= 1) {
                int v = __shfl_up_sync(0xffffffffu, ws, d);
                if (lane >= d) ws += v;
            }
            warp_sums[lane] = ws;
        }
        __syncthreads();
        int warp_off = (wid > 0) ? warp_sums[wid - 1] : 0;
        if (i < N) g_off[i] = s_carry + warp_off + inc - x;
        int block_total = warp_sums[31];
        __syncthreads();
        if (t == 0) s_carry += block_total;
        __syncthreads();
    }
}

__global__ void scatter_kernel(const int* __restrict__ src, const int* __restrict__ dst, int E)
{
    int i = blockIdx.x * blockDim.x + threadIdx.x;
    if (i < E) {
        int d = dst[i];
        int p = atomicAdd(&g_off[d], 1);
        g_src_sorted[p] = src[i];
    }
}

// ---------------------------------------------------------------------------
// Kernel 3: warp-per-dst attention over interleaved fp16 KV, unroll-4.
// Lane l owns dims [4l,4l+4) => head l>>2. Q fp32.
// ---------------------------------------------------------------------------
struct Half4 { __half2 a, b; };

__device__ __forceinline__ float4 h4_to_f4(Half4 x) {
    float2 lo = __half22float2(x.a), hi = __half22float2(x.b);
    return make_float4(lo.x, lo.y, hi.x, hi.y);
}

__global__ void attn_kernel(float* __restrict__ out, int N)
{
    const int lane = threadIdx.x & 31;
    const int w = (blockIdx.x * blockDim.x + threadIdx.x) >> 5;
    if (w >= N) return;

    const int beg = (w == 0) ? 0 : __ldg(&g_off[w - 1]);
    const int end = __ldg(&g_off[w]);

    const float4 q = *reinterpret_cast<const float4*>(g_Q + (size_t)w * HD + lane * 4);

    float4 av = make_float4(0.f, 0.f, 0.f, 0.f);
    float z = 0.f;

    int e = beg;
    for (; e + 4 <= end; e += 4) {
        int s[4];
#pragma unroll
        for (int j = 0; j < 4; j++) s[j] = __ldg(&g_src_sorted[e + j]);

        Half4 K[4], V[4];
#pragma unroll
        for (int j = 0; j < 4; j++) {
            const __half* kv = g_KVh + (size_t)s[j] * 256;
            K[j] = *reinterpret_cast<const Half4*>(kv + lane * 4);
            V[j] = *reinterpret_cast<const Half4*>(kv + 128 + lane * 4);
        }

        float sc[4];
#pragma unroll
        for (int j = 0; j < 4; j++) {
            const float4 k = h4_to_f4(K[j]);
            sc[j] = q.x * k.x + q.y * k.y + q.z * k.z + q.w * k.w;
        }
#pragma unroll
        for (int j = 0; j < 4; j++) sc[j] += __shfl_xor_sync(0xffffffffu, sc[j], 1);
#pragma unroll
        for (int j = 0; j < 4; j++) sc[j] += __shfl_xor_sync(0xffffffffu, sc[j], 2);
#pragma unroll
        for (int j = 0; j < 4; j++) sc[j] = __expf(fminf(fmaxf(sc[j], -5.f), 5.f));

#pragma unroll
        for (int j = 0; j < 4; j++) {
            const float4 v = h4_to_f4(V[j]);
            av.x = fmaf(v.x, sc[j], av.x); av.y = fmaf(v.y, sc[j], av.y);
            av.z = fmaf(v.z, sc[j], av.z); av.w = fmaf(v.w, sc[j], av.w);
        }
        if ((lane & 3) == 0) z += (sc[0] + sc[1]) + (sc[2] + sc[3]);
    }
    for (; e < end; e++) {
        const int s0 = __ldg(&g_src_sorted[e]);
        const __half* kv = g_KVh + (size_t)s0 * 256;
        const Half4 K0 = *reinterpret_cast<const Half4*>(kv + lane * 4);
        const float4 k0 = h4_to_f4(K0);
        float sc0 = q.x * k0.x + q.y * k0.y + q.z * k0.z + q.w * k0.w;
        sc0 += __shfl_xor_sync(0xffffffffu, sc0, 1);
        sc0 += __shfl_xor_sync(0xffffffffu, sc0, 2);
        sc0 = __expf(fminf(fmaxf(sc0, -5.f), 5.f));
        const Half4 V0 = *reinterpret_cast<const Half4*>(kv + 128 + lane * 4);
        const float4 v0 = h4_to_f4(V0);
        av.x = fmaf(v0.x, sc0, av.x); av.y = fmaf(v0.y, sc0, av.y);
        av.z = fmaf(v0.z, sc0, av.z); av.w = fmaf(v0.w, sc0, av.w);
        if ((lane & 3) == 0) z += sc0;
    }

    z = __shfl_sync(0xffffffffu, z, lane & ~3);
    const float inv = 1.f / z;

    float4 o;
    o.x = av.x * inv; o.y = av.y * inv; o.z = av.z * inv; o.w = av.w * inv;
    *reinterpret_cast<float4*>(out + (size_t)w * HD + lane * 4) = o;
}

// ---------------------------------------------------------------------------
extern "C" void kernel_launch(void* const* d_in, const int* in_sizes, int n_in,
                              void* d_out, int out_size)
{
    const float* h  = (const float*)d_in[0];
    const int* src  = (const int*)d_in[1];
    const int* dst  = (const int*)d_in[2];
    const float* Wq = (const float*)d_in[3];
    const float* Wk = (const float*)d_in[4];
    const float* Wv = (const float*)d_in[5];
    const float* bq = (const float*)d_in[6];
    const float* bk = (const float*)d_in[7];
    const float* bv = (const float*)d_in[8];
    float* out = (float*)d_out;

    const int N = in_sizes[0] / IN_DIM;
    const int E = in_sizes[1];

    // One-time setup on the uncaptured correctness call
    static cudaStream_t s2 = nullptr;
    static cudaEvent_t evFork = nullptr, evJoin = nullptr;
    static void* degptr = nullptr;
    if (s2 == nullptr) {
        cudaStreamCreateWithFlags(&s2, cudaStreamNonBlocking);
        cudaEventCreateWithFlags(&evFork, cudaEventDisableTiming);
        cudaEventCreateWithFlags(&evJoin, cudaEventDisableTiming);
        cudaGetSymbolAddress(&degptr, g_deg);
        cudaFuncSetAttribute(qkv_mma_kernel, cudaFuncAttributeMaxDynamicSharedMemorySize,
                             QKV_SMEM);
    }

    const int eb = (E + 255) / 256;

    // Fork: CSR build on s2; W prepass + tensor GEMM on the main stream.
    cudaEventRecord(evFork, 0);
    cudaStreamWaitEvent(s2, evFork, 0);

    cudaMemsetAsync(degptr, 0, (size_t)N * sizeof(int), s2);
    hist_kernel<<<eb, 256, 0, s2>>>(dst, E);
    scan_kernel<<<1, 1024, 0, s2>>>(N);
    scatter_kernel<<<eb, 256, 0, s2>>>(src, dst, E);
    cudaEventRecord(evJoin, s2);

    wprep_kernel<<<(3 * 128 * 128 + 255) / 256, 256>>>(Wq, Wk, Wv);
    dim3 qkv_grid((N + 127) / 128, 3);
    qkv_mma_kernel<<<qkv_grid, 256, QKV_SMEM>>>(h, bq, bk, bv, N);

    // Join, then attention (warp per dst node)
    cudaStreamWaitEvent(0, evJoin, 0);
    attn_kernel<<<(N * 32 + 255) / 256, 256>>>(out, N);
}

// round 13
// speedup vs baseline: 1.2502x; 1.2502x over previous
#include <cuda_runtime.h>
#include <cuda_bf16.h>
#include <cuda_fp16.h>
#include <cstdint>

// Problem constants
#define MAXN 50000
#define MAXE 800000
#define IN_DIM 128
#define HD 128
#define ASTRIDE 136               // fp16 elems per smem row (272B, conflict-free ldmatrix)
#define IMG_BYTES (128 * ASTRIDE * 2)           // 34816 B per image
#define QKV_SMEM (2 * IMG_BYTES)                // A, B = 69632 B

// ---- scratch (static device arrays; no allocation allowed) ----
__device__ float  g_Q[(size_t)MAXN * HD];    // pre-scaled by 0.25, fp32
__device__ __half g_Kh[(size_t)MAXN * HD];   // fp16
__device__ __half g_Vh[(size_t)MAXN * HD];   // fp16
__device__ int    g_deg[MAXN];
__device__ int    g_off[MAXN];               // after scatter: g_off[d] = segment END of d
__device__ int    g_src_sorted[MAXE];
// W^T fp16 padded images: [matrix][n=128 rows][ASTRIDE k-cols]
__device__ __half g_Bimg[3][128 * ASTRIDE];

__device__ __forceinline__ uint32_t smem_u32(const void* p) {
    uint32_t a;
    asm("{ .reg .u64 t; cvta.to.shared.u64 t, %1; cvt.u32.u64 %0, t; }" : "=r"(a) : "l"(p));
    return a;
}

#define LDSM_X4(r0, r1, r2, r3, addr)                                            \
    asm volatile("ldmatrix.sync.aligned.m8n8.x4.shared.b16 {%0,%1,%2,%3}, [%4];" \
                 : "=r"(r0), "=r"(r1), "=r"(r2), "=r"(r3) : "r"(addr))

#define MMA16816F(c, a0, a1, a2, a3, b0, b1)                                     \
    asm volatile("mma.sync.aligned.m16n8k16.row.col.f32.f16.f16.f32 "            \
                 "{%0,%1,%2,%3}, {%4,%5,%6,%7}, {%8,%9}, {%0,%1,%2,%3};"         \
                 : "+f"((c)[0]), "+f"((c)[1]), "+f"((c)[2]), "+f"((c)[3])        \
                 : "r"(a0), "r"(a1), "r"(a2), "r"(a3), "r"(b0), "r"(b1))

// ---------------------------------------------------------------------------
// Prepass: W^T fp16 padded images. B[n][k] = W[k][n].
// ---------------------------------------------------------------------------
__global__ void wprep_kernel(const float* __restrict__ Wq,
                             const float* __restrict__ Wk,
                             const float* __restrict__ Wv)
{
    int idx = blockIdx.x * blockDim.x + threadIdx.x;
    if (idx >= 3 * 128 * 128) return;
    int m = idx >> 14, rem = idx & 16383, n = rem >> 7, k = rem & 127;
    const float* W = (m == 0) ? Wq : ((m == 1) ? Wk : Wv);
    g_Bimg[m][n * ASTRIDE + k] = __float2half_rn(W[k * 128 + n]);
}

// ---------------------------------------------------------------------------
// Kernel 1: QKV projection via mma.sync fp16 single-product GEMM.
// Block: 128 nodes x 128 cols, 256 threads (8 warps: 4 m-chunks x 2 n-chunks).
// A = fp16(h), B = fp16(W^T); acc = A*B (fp32 accum). Stage A once, loop m
// over the 3 prebuilt B images (round-10 proven structure).
// ---------------------------------------------------------------------------
__global__ void __launch_bounds__(256, 2) qkv_mma_kernel(
    const float* __restrict__ h,
    const float* __restrict__ bq, const float* __restrict__ bk, const float* __restrict__ bv,
    int N)
{
    extern __shared__ __half smem[];
    __half* As = smem;                       // [row][k]
    __half* Bs = smem + 128 * ASTRIDE;       // [n][k]

    const int tid = threadIdx.x;
    const int lane = tid & 31, warp = tid >> 5;
    const int wm = warp & 3;       // m-chunk: rows [32*wm, 32*wm+32)
    const int wn = warp >> 2;      // n-chunk: cols [64*wn, 64*wn+64)
    const int node0 = blockIdx.x * 128;

    // ---- Stage A: fp32 -> fp16. Thread t: row t>>1, col-half t&1. ----
    {
        const int r = tid >> 1, cb = (tid & 1) * 64;
        const bool valid = (node0 + r) < N;
        const float* hp = h + (size_t)(node0 + r) * IN_DIM + cb;
        __half* ap = As + r * ASTRIDE + cb;
#pragma unroll
        for (int i = 0; i < 64; i += 4) {
            float4 v = valid ? *reinterpret_cast<const float4*>(hp + i)
                             : make_float4(0.f, 0.f, 0.f, 0.f);
            *reinterpret_cast<__half2*>(ap + i)     = __floats2half2_rn(v.x, v.y);
            *reinterpret_cast<__half2*>(ap + i + 2) = __floats2half2_rn(v.z, v.w);
        }
    }

    const uint32_t uAs = smem_u32(As);
    const uint32_t uBs = smem_u32(Bs);

    // A: row = wm*32 + mt*16 + (lane&15); byte += (lane>>4)*16 + kk*32
    const uint32_t aRow = (uint32_t)(wm * 32 + (lane & 15)) * 272u + (uint32_t)(lane >> 4) * 16u;
    // B: n-row = wn*64 + p*16 + ((lane>>4)&1)*8 + (lane&7); byte += ((lane>>3)&1)*16 + kk*32
    const uint32_t bRow = (uint32_t)(wn * 64 + ((lane >> 4) & 1) * 8 + (lane & 7)) * 272u
                        + (uint32_t)((lane >> 3) & 1) * 16u;

    const float* biases[3] = {bq, bk, bv};

    for (int m = 0; m < 3; m++) {
        // ---- Stage B (single fp16 image of matrix m) ----
        __syncthreads();
        {
            const float4* sb = reinterpret_cast<const float4*>(g_Bimg[m]);
            float4* db = reinterpret_cast<float4*>(Bs);
            for (int i = tid; i < IMG_BYTES / 16; i += 256) db[i] = sb[i];
        }
        __syncthreads();

        float acc[2][8][4];
#pragma unroll
        for (int mt = 0; mt < 2; mt++)
#pragma unroll
            for (int nt = 0; nt < 8; nt++)
#pragma unroll
                for (int c = 0; c < 4; c++) acc[mt][nt][c] = 0.f;

#pragma unroll
        for (int kk = 0; kk < 8; kk++) {
            const uint32_t kO = (uint32_t)kk * 32u;

            uint32_t ah[2][4];
#pragma unroll
            for (int mt = 0; mt < 2; mt++) {
                const uint32_t ro = aRow + (uint32_t)(mt * 16) * 272u + kO;
                LDSM_X4(ah[mt][0], ah[mt][1], ah[mt][2], ah[mt][3], uAs + ro);
            }

            uint32_t bf[8][2];
#pragma unroll
            for (int p = 0; p < 4; p++) {
                const uint32_t ro = bRow + (uint32_t)(p * 16) * 272u + kO;
                LDSM_X4(bf[2 * p][0], bf[2 * p][1], bf[2 * p + 1][0], bf[2 * p + 1][1], uBs + ro);
            }

#pragma unroll
            for (int mt = 0; mt < 2; mt++)
#pragma unroll
                for (int nt = 0; nt < 8; nt++)
                    MMA16816F(acc[mt][nt], ah[mt][0], ah[mt][1], ah[mt][2], ah[mt][3],
                              bf[nt][0], bf[nt][1]);
        }

        // ---- Epilogue ----
        const float* bb = biases[m];
#pragma unroll
        for (int mt = 0; mt < 2; mt++) {
            const int r0 = node0 + wm * 32 + mt * 16 + (lane >> 2);
#pragma unroll
            for (int nt = 0; nt < 8; nt++) {
                const int col = wn * 64 + nt * 8 + (lane & 3) * 2;
                const float b0 = __ldg(bb + col), b1 = __ldg(bb + col + 1);
                if (m == 0) {
                    if (r0 < N) {
                        float2 o = make_float2((acc[mt][nt][0] + b0) * 0.25f,
                                               (acc[mt][nt][1] + b1) * 0.25f);
                        *reinterpret_cast<float2*>(g_Q + (size_t)r0 * HD + col) = o;
                    }
                    if (r0 + 8 < N) {
                        float2 o = make_float2((acc[mt][nt][2] + b0) * 0.25f,
                                               (acc[mt][nt][3] + b1) * 0.25f);
                        *reinterpret_cast<float2*>(g_Q + (size_t)(r0 + 8) * HD + col) = o;
                    }
                } else {
                    __half* dstp = (m == 1) ? g_Kh : g_Vh;
                    if (r0 < N) {
                        __half2 o = __floats2half2_rn(acc[mt][nt][0] + b0,
                                                      acc[mt][nt][1] + b1);
                        *reinterpret_cast<__half2*>(dstp + (size_t)r0 * HD + col) = o;
                    }
                    if (r0 + 8 < N) {
                        __half2 o = __floats2half2_rn(acc[mt][nt][2] + b0,
                                                      acc[mt][nt][3] + b1);
                        *reinterpret_cast<__half2*>(dstp + (size_t)(r0 + 8) * HD + col) = o;
                    }
                }
            }
        }
    }
}

// ---------------------------------------------------------------------------
// CSR build: hist -> single-block scan -> scatter (atomic bump on g_off)
// ---------------------------------------------------------------------------
__global__ void hist_kernel(const int* __restrict__ dst, int E)
{
    int i = blockIdx.x * blockDim.x + threadIdx.x;
    if (i < E) atomicAdd(&g_deg[dst[i]], 1);
}

__global__ __launch_bounds__(1024) void scan_kernel(int N)
{
    __shared__ int warp_sums[32];
    __shared__ int s_carry;
    const int t = threadIdx.x;
    const int lane = t & 31, wid = t >> 5;
    if (t == 0) s_carry = 0;
    __syncthreads();

    for (int base = 0; base < N; base += 1024) {
        int i = base + t;
        int x = (i < N) ? g_deg[i] : 0;
        int inc = x;
#pragma unroll
        for (int d = 1; d < 32; d <<= 1) {
            int v = __shfl_up_sync(0xffffffffu, inc, d);
            if (lane >= d) inc += v;
        }
        if (lane == 31) warp_sums[wid] = inc;
        __syncthreads();
        if (wid == 0) {
            int ws = warp_sums[lane];
#pragma unroll
            for (int d = 1; d < 32; d <<= 1) {
                int v = __shfl_up_sync(0xffffffffu, ws, d);
                if (lane >= d) ws += v;
            }
            warp_sums[lane] = ws;
        }
        __syncthreads();
        int warp_off = (wid > 0) ? warp_sums[wid - 1] : 0;
        if (i < N) g_off[i] = s_carry + warp_off + inc - x;
        int block_total = warp_sums[31];
        __syncthreads();
        if (t == 0) s_carry += block_total;
        __syncthreads();
    }
}

__global__ void scatter_kernel(const int* __restrict__ src, const int* __restrict__ dst, int E)
{
    int i = blockIdx.x * blockDim.x + threadIdx.x;
    if (i < E) {
        int d = dst[i];
        int p = atomicAdd(&g_off[d], 1);
        g_src_sorted[p] = src[i];
    }
}

// ---------------------------------------------------------------------------
// Kernel 3: warp-per-dst attention over fp16 K/V, unroll-4.
// Lane l owns dims [4l,4l+4) => head l>>2. Q fp32.
// ---------------------------------------------------------------------------
struct Half4 { __half2 a, b; };

__device__ __forceinline__ float4 h4_to_f4(Half4 x) {
    float2 lo = __half22float2(x.a), hi = __half22float2(x.b);
    return make_float4(lo.x, lo.y, hi.x, hi.y);
}

__global__ void attn_kernel(float* __restrict__ out, int N)
{
    const int lane = threadIdx.x & 31;
    const int w = (blockIdx.x * blockDim.x + threadIdx.x) >> 5;
    if (w >= N) return;

    const int beg = (w == 0) ? 0 : __ldg(&g_off[w - 1]);
    const int end = __ldg(&g_off[w]);

    const float4 q = *reinterpret_cast<const float4*>(g_Q + (size_t)w * HD + lane * 4);

    float4 av = make_float4(0.f, 0.f, 0.f, 0.f);
    float z = 0.f;

    int e = beg;
    for (; e + 4 <= end; e += 4) {
        int s[4];
#pragma unroll
        for (int j = 0; j < 4; j++) s[j] = __ldg(&g_src_sorted[e + j]);

        Half4 K[4], V[4];
#pragma unroll
        for (int j = 0; j < 4; j++) {
            K[j] = *reinterpret_cast<const Half4*>(g_Kh + (size_t)s[j] * HD + lane * 4);
            V[j] = *reinterpret_cast<const Half4*>(g_Vh + (size_t)s[j] * HD + lane * 4);
        }

        float sc[4];
#pragma unroll
        for (int j = 0; j < 4; j++) {
            const float4 k = h4_to_f4(K[j]);
            sc[j] = q.x * k.x + q.y * k.y + q.z * k.z + q.w * k.w;
        }
#pragma unroll
        for (int j = 0; j < 4; j++) sc[j] += __shfl_xor_sync(0xffffffffu, sc[j], 1);
#pragma unroll
        for (int j = 0; j < 4; j++) sc[j] += __shfl_xor_sync(0xffffffffu, sc[j], 2);
#pragma unroll
        for (int j = 0; j < 4; j++) sc[j] = __expf(fminf(fmaxf(sc[j], -5.f), 5.f));

#pragma unroll
        for (int j = 0; j < 4; j++) {
            const float4 v = h4_to_f4(V[j]);
            av.x = fmaf(v.x, sc[j], av.x); av.y = fmaf(v.y, sc[j], av.y);
            av.z = fmaf(v.z, sc[j], av.z); av.w = fmaf(v.w, sc[j], av.w);
        }
        if ((lane & 3) == 0) z += (sc[0] + sc[1]) + (sc[2] + sc[3]);
    }
    for (; e < end; e++) {
        const int s0 = __ldg(&g_src_sorted[e]);
        const Half4 K0 = *reinterpret_cast<const Half4*>(g_Kh + (size_t)s0 * HD + lane * 4);
        const float4 k0 = h4_to_f4(K0);
        float sc0 = q.x * k0.x + q.y * k0.y + q.z * k0.z + q.w * k0.w;
        sc0 += __shfl_xor_sync(0xffffffffu, sc0, 1);
        sc0 += __shfl_xor_sync(0xffffffffu, sc0, 2);
        sc0 = __expf(fminf(fmaxf(sc0, -5.f), 5.f));
        const Half4 V0 = *reinterpret_cast<const Half4*>(g_Vh + (size_t)s0 * HD + lane * 4);
        const float4 v0 = h4_to_f4(V0);
        av.x = fmaf(v0.x, sc0, av.x); av.y = fmaf(v0.y, sc0, av.y);
        av.z = fmaf(v0.z, sc0, av.z); av.w = fmaf(v0.w, sc0, av.w);
        if ((lane & 3) == 0) z += sc0;
    }

    z = __shfl_sync(0xffffffffu, z, lane & ~3);
    const float inv = 1.f / z;

    float4 o;
    o.x = av.x * inv; o.y = av.y * inv; o.z = av.z * inv; o.w = av.w * inv;
    *reinterpret_cast<float4*>(out + (size_t)w * HD + lane * 4) = o;
}

// ---------------------------------------------------------------------------
extern "C" void kernel_launch(void* const* d_in, const int* in_sizes, int n_in,
                              void* d_out, int out_size)
{
    const float* h  = (const float*)d_in[0];
    const int* src  = (const int*)d_in[1];
    const int* dst  = (const int*)d_in[2];
    const float* Wq = (const float*)d_in[3];
    const float* Wk = (const float*)d_in[4];
    const float* Wv = (const float*)d_in[5];
    const float* bq = (const float*)d_in[6];
    const float* bk = (const float*)d_in[7];
    const float* bv = (const float*)d_in[8];
    float* out = (float*)d_out;

    const int N = in_sizes[0] / IN_DIM;
    const int E = in_sizes[1];

    // One-time setup on the uncaptured correctness call
    static cudaStream_t s2 = nullptr;
    static cudaEvent_t evFork = nullptr, evJoin = nullptr;
    static void* degptr = nullptr;
    if (s2 == nullptr) {
        cudaStreamCreateWithFlags(&s2, cudaStreamNonBlocking);
        cudaEventCreateWithFlags(&evFork, cudaEventDisableTiming);
        cudaEventCreateWithFlags(&evJoin, cudaEventDisableTiming);
        cudaGetSymbolAddress(&degptr, g_deg);
        cudaFuncSetAttribute(qkv_mma_kernel, cudaFuncAttributeMaxDynamicSharedMemorySize,
                             QKV_SMEM);
    }

    const int eb = (E + 255) / 256;

    // Fork: CSR build on s2; W prepass + tensor GEMM on the main stream.
    cudaEventRecord(evFork, 0);
    cudaStreamWaitEvent(s2, evFork, 0);

    cudaMemsetAsync(degptr, 0, (size_t)N * sizeof(int), s2);
    hist_kernel<<<eb, 256, 0, s2>>>(dst, E);
    scan_kernel<<<1, 1024, 0, s2>>>(N);
    scatter_kernel<<<eb, 256, 0, s2>>>(src, dst, E);
    cudaEventRecord(evJoin, s2);

    wprep_kernel<<<(3 * 128 * 128 + 255) / 256, 256>>>(Wq, Wk, Wv);
    qkv_mma_kernel<<<(N + 127) / 128, 256, QKV_SMEM>>>(h, bq, bk, bv, N);

    // Join, then attention (warp per dst node)
    cudaStreamWaitEvent(0, evJoin, 0);
    attn_kernel<<<(N * 32 + 255) / 256, 256>>>(out, N);
}

// round 15
// speedup vs baseline: 1.5139x; 1.2110x over previous
#include <cuda_runtime.h>
#include <cuda_bf16.h>
#include <cuda_fp16.h>
#include <cstdint>

// Problem constants
#define MAXN 50000
#define MAXE 800000
#define IN_DIM 128
#define HD 128
#define ASTRIDE 136               // fp16 elems per smem row (272B, conflict-free ldmatrix)
#define IMG_BYTES (128 * ASTRIDE * 2)           // 34816 B per image
#define QKV_SMEM (3 * IMG_BYTES)                // A + 2x B double-buffer = 104448 B

// ---- scratch (static device arrays; no allocation allowed) ----
__device__ float  g_Q[(size_t)MAXN * HD];    // pre-scaled by 0.25, fp32
__device__ __half g_Kh[(size_t)MAXN * HD];   // fp16
__device__ __half g_Vh[(size_t)MAXN * HD];   // fp16
__device__ int    g_deg[MAXN];
__device__ int    g_off[MAXN];               // after scatter: g_off[d] = segment END of d
__device__ int    g_chsum[64];
__device__ int    g_src_sorted[MAXE];
// W^T fp16 padded images: [matrix][n=128 rows][ASTRIDE k-cols]
__device__ alignas(16) __half g_Bimg[3][128 * ASTRIDE];

__device__ __forceinline__ uint32_t smem_u32(const void* p) {
    uint32_t a;
    asm("{ .reg .u64 t; cvta.to.shared.u64 t, %1; cvt.u32.u64 %0, t; }" : "=r"(a) : "l"(p));
    return a;
}

#define LDSM_X4(r0, r1, r2, r3, addr)                                            \
    asm volatile("ldmatrix.sync.aligned.m8n8.x4.shared.b16 {%0,%1,%2,%3}, [%4];" \
                 : "=r"(r0), "=r"(r1), "=r"(r2), "=r"(r3) : "r"(addr))

#define MMA16816F(c, a0, a1, a2, a3, b0, b1)                                     \
    asm volatile("mma.sync.aligned.m16n8k16.row.col.f32.f16.f16.f32 "            \
                 "{%0,%1,%2,%3}, {%4,%5,%6,%7}, {%8,%9}, {%0,%1,%2,%3};"         \
                 : "+f"((c)[0]), "+f"((c)[1]), "+f"((c)[2]), "+f"((c)[3])        \
                 : "r"(a0), "r"(a1), "r"(a2), "r"(a3), "r"(b0), "r"(b1))

// ---------------------------------------------------------------------------
// Prepass: W^T fp16 padded images. B[n][k] = W[k][n].
// ---------------------------------------------------------------------------
__global__ void wprep_kernel(const float* __restrict__ Wq,
                             const float* __restrict__ Wk,
                             const float* __restrict__ Wv)
{
    int idx = blockIdx.x * blockDim.x + threadIdx.x;
    if (idx >= 3 * 128 * 128) return;
    int m = idx >> 14, rem = idx & 16383, n = rem >> 7, k = rem & 127;
    const float* W = (m == 0) ? Wq : ((m == 1) ? Wk : Wv);
    g_Bimg[m][n * ASTRIDE + k] = __float2half_rn(W[k * 128 + n]);
}

// Issue async copy of one B image into smem (16B granules), then commit.
__device__ __forceinline__ void stageB_async(const __half* src, uint32_t dstBase, int tid)
{
    const char* sp = reinterpret_cast<const char*>(src);
#pragma unroll
    for (int i = tid * 16; i < IMG_BYTES; i += 256 * 16) {
        asm volatile("cp.async.cg.shared.global [%0], [%1], 16;"
                     :: "r"(dstBase + (uint32_t)i), "l"(sp + i));
    }
    asm volatile("cp.async.commit_group;");
}

// ---------------------------------------------------------------------------
// Kernel 1: QKV projection via mma.sync fp16 GEMM, cp.async double-buffered B.
// Block: 128 nodes x 128 cols, 256 threads (8 warps: 4 m-chunks x 2 n-chunks).
// A = fp16(h), B = fp16(W^T); B[m+1] streams in while m computes.
// ---------------------------------------------------------------------------
__global__ void __launch_bounds__(256, 2) qkv_mma_kernel(
    const float* __restrict__ h,
    const float* __restrict__ bq, const float* __restrict__ bk, const float* __restrict__ bv,
    int N)
{
    extern __shared__ __half smem[];
    __half* As = smem;                           // [row][k]
    const uint32_t uAs  = smem_u32(As);
    const uint32_t uBs0 = uAs + (uint32_t)IMG_BYTES;
    const uint32_t uBs1 = uBs0 + (uint32_t)IMG_BYTES;

    const int tid = threadIdx.x;
    const int lane = tid & 31, warp = tid >> 5;
    const int wm = warp & 3;       // m-chunk: rows [32*wm, 32*wm+32)
    const int wn = warp >> 2;      // n-chunk: cols [64*wn, 64*wn+64)
    const int node0 = blockIdx.x * 128;

    // Kick off B[0] copy immediately.
    stageB_async(g_Bimg[0], uBs0, tid);

    // ---- Stage A: fp32 -> fp16. Thread t: row t>>1, col-half t&1. ----
    {
        const int r = tid >> 1, cb = (tid & 1) * 64;
        const bool valid = (node0 + r) < N;
        const float* hp = h + (size_t)(node0 + r) * IN_DIM + cb;
        __half* ap = As + r * ASTRIDE + cb;
#pragma unroll
        for (int i = 0; i < 64; i += 4) {
            float4 v = valid ? *reinterpret_cast<const float4*>(hp + i)
                             : make_float4(0.f, 0.f, 0.f, 0.f);
            *reinterpret_cast<__half2*>(ap + i)     = __floats2half2_rn(v.x, v.y);
            *reinterpret_cast<__half2*>(ap + i + 2) = __floats2half2_rn(v.z, v.w);
        }
    }
    asm volatile("cp.async.wait_group 0;" ::: "memory");
    __syncthreads();

    // A: row = wm*32 + mt*16 + (lane&15); byte += (lane>>4)*16 + kk*32
    const uint32_t aRow = (uint32_t)(wm * 32 + (lane & 15)) * 272u + (uint32_t)(lane >> 4) * 16u;
    // B: n-row = wn*64 + p*16 + ((lane>>4)&1)*8 + (lane&7); byte += ((lane>>3)&1)*16 + kk*32
    const uint32_t bRow = (uint32_t)(wn * 64 + ((lane >> 4) & 1) * 8 + (lane & 7)) * 272u
                        + (uint32_t)((lane >> 3) & 1) * 16u;

    const float* biases[3] = {bq, bk, bv};

#pragma unroll
    for (int m = 0; m < 3; m++) {
        const uint32_t uCur = (m & 1) ? uBs1 : uBs0;
        // Prefetch next B image into the other buffer (overlaps the MMAs).
        if (m < 2) stageB_async(g_Bimg[m + 1], (m & 1) ? uBs0 : uBs1, tid);

        float acc[2][8][4];
#pragma unroll
        for (int mt = 0; mt < 2; mt++)
#pragma unroll
            for (int nt = 0; nt < 8; nt++)
#pragma unroll
                for (int c = 0; c < 4; c++) acc[mt][nt][c] = 0.f;

#pragma unroll
        for (int kk = 0; kk < 8; kk++) {
            const uint32_t kO = (uint32_t)kk * 32u;

            uint32_t ah[2][4];
#pragma unroll
            for (int mt = 0; mt < 2; mt++) {
                const uint32_t ro = aRow + (uint32_t)(mt * 16) * 272u + kO;
                LDSM_X4(ah[mt][0], ah[mt][1], ah[mt][2], ah[mt][3], uAs + ro);
            }

            uint32_t bf[8][2];
#pragma unroll
            for (int p = 0; p < 4; p++) {
                const uint32_t ro = bRow + (uint32_t)(p * 16) * 272u + kO;
                LDSM_X4(bf[2 * p][0], bf[2 * p][1], bf[2 * p + 1][0], bf[2 * p + 1][1], uCur + ro);
            }

#pragma unroll
            for (int mt = 0; mt < 2; mt++)
#pragma unroll
                for (int nt = 0; nt < 8; nt++)
                    MMA16816F(acc[mt][nt], ah[mt][0], ah[mt][1], ah[mt][2], ah[mt][3],
                              bf[nt][0], bf[nt][1]);
        }

        // ---- Epilogue (register-only + global stores; overlaps cp.async) ----
        const float* bb = biases[m];
#pragma unroll
        for (int mt = 0; mt < 2; mt++) {
            const int r0 = node0 + wm * 32 + mt * 16 + (lane >> 2);
#pragma unroll
            for (int nt = 0; nt < 8; nt++) {
                const int col = wn * 64 + nt * 8 + (lane & 3) * 2;
                const float b0 = __ldg(bb + col), b1 = __ldg(bb + col + 1);
                if (m == 0) {
                    if (r0 < N) {
                        float2 o = make_float2((acc[mt][nt][0] + b0) * 0.25f,
                                               (acc[mt][nt][1] + b1) * 0.25f);
                        *reinterpret_cast<float2*>(g_Q + (size_t)r0 * HD + col) = o;
                    }
                    if (r0 + 8 < N) {
                        float2 o = make_float2((acc[mt][nt][2] + b0) * 0.25f,
                                               (acc[mt][nt][3] + b1) * 0.25f);
                        *reinterpret_cast<float2*>(g_Q + (size_t)(r0 + 8) * HD + col) = o;
                    }
                } else {
                    __half* dstp = (m == 1) ? g_Kh : g_Vh;
                    if (r0 < N) {
                        __half2 o = __floats2half2_rn(acc[mt][nt][0] + b0,
                                                      acc[mt][nt][1] + b1);
                        *reinterpret_cast<__half2*>(dstp + (size_t)r0 * HD + col) = o;
                    }
                    if (r0 + 8 < N) {
                        __half2 o = __floats2half2_rn(acc[mt][nt][2] + b0,
                                                      acc[mt][nt][3] + b1);
                        *reinterpret_cast<__half2*>(dstp + (size_t)(r0 + 8) * HD + col) = o;
                    }
                }
            }
        }

        if (m < 2) {
            asm volatile("cp.async.wait_group 0;" ::: "memory");
            __syncthreads();
        }
    }
}

// ---------------------------------------------------------------------------
// CSR build: hist -> parallel 2-kernel scan -> scatter (atomic bump on g_off)
// ---------------------------------------------------------------------------
__global__ void hist_kernel(const int* __restrict__ dst, int E)
{
    int i = blockIdx.x * blockDim.x + threadIdx.x;
    if (i < E) atomicAdd(&g_deg[dst[i]], 1);
}

// scanA: per-chunk exclusive scan (1024/chunk), chunk totals to g_chsum.
__global__ __launch_bounds__(1024) void scanA_kernel(int N)
{
    __shared__ int warp_sums[32];
    const int t = threadIdx.x, lane = t & 31, wid = t >> 5;
    const int i = blockIdx.x * 1024 + t;
    int x = (i < N) ? g_deg[i] : 0;
    int inc = x;
#pragma unroll
    for (int d = 1; d < 32; d <<= 1) {
        int v = __shfl_up_sync(0xffffffffu, inc, d);
        if (lane >= d) inc += v;
    }
    if (lane == 31) warp_sums[wid] = inc;
    __syncthreads();
    if (wid == 0) {
        int ws = warp_sums[lane];
#pragma unroll
        for (int d = 1; d < 32; d <<= 1) {
            int v = __shfl_up_sync(0xffffffffu, ws, d);
            if (lane >= d) ws += v;
        }
        warp_sums[lane] = ws;
    }
    __syncthreads();
    int base = (wid > 0) ? warp_sums[wid - 1] : 0;
    if (i < N) g_off[i] = base + inc - x;   // exclusive within chunk
    if (t == 0) g_chsum[blockIdx.x] = warp_sums[31];
}

// scanB: each chunk adds the prefix of chunk sums (warp-strided reduce).
__global__ __launch_bounds__(1024) void scanB_kernel(int N)
{
    __shared__ int s_base;
    const int t = threadIdx.x;
    if (t < 32) {
        int v = 0;
        for (int j = t; j < blockIdx.x; j += 32) v += g_chsum[j];
#pragma unroll
        for (int d = 16; d; d >>= 1) v += __shfl_xor_sync(0xffffffffu, v, d);
        if (t == 0) s_base = v;
    }
    __syncthreads();
    const int i = blockIdx.x * 1024 + t;
    if (i < N && blockIdx.x > 0) g_off[i] += s_base;
}

__global__ void scatter_kernel(const int* __restrict__ src, const int* __restrict__ dst, int E)
{
    int i = blockIdx.x * blockDim.x + threadIdx.x;
    if (i < E) {
        int d = dst[i];
        int p = atomicAdd(&g_off[d], 1);
        g_src_sorted[p] = src[i];
    }
}

// ---------------------------------------------------------------------------
// Kernel 3: warp-per-dst attention over fp16 K/V, unroll-4.
// Lane l owns dims [4l,4l+4) => head l>>2. Q fp32.
// ---------------------------------------------------------------------------
struct Half4 { __half2 a, b; };

__device__ __forceinline__ float4 h4_to_f4(Half4 x) {
    float2 lo = __half22float2(x.a), hi = __half22float2(x.b);
    return make_float4(lo.x, lo.y, hi.x, hi.y);
}

__global__ void attn_kernel(float* __restrict__ out, int N)
{
    const int lane = threadIdx.x & 31;
    const int w = (blockIdx.x * blockDim.x + threadIdx.x) >> 5;
    if (w >= N) return;

    const int beg = (w == 0) ? 0 : __ldg(&g_off[w - 1]);
    const int end = __ldg(&g_off[w]);

    const float4 q = *reinterpret_cast<const float4*>(g_Q + (size_t)w * HD + lane * 4);

    float4 av = make_float4(0.f, 0.f, 0.f, 0.f);
    float z = 0.f;

    int e = beg;
    for (; e + 4 <= end; e += 4) {
        int s[4];
#pragma unroll
        for (int j = 0; j < 4; j++) s[j] = __ldg(&g_src_sorted[e + j]);

        Half4 K[4], V[4];
#pragma unroll
        for (int j = 0; j < 4; j++) {
            K[j] = *reinterpret_cast<const Half4*>(g_Kh + (size_t)s[j] * HD + lane * 4);
            V[j] = *reinterpret_cast<const Half4*>(g_Vh + (size_t)s[j] * HD + lane * 4);
        }

        float sc[4];
#pragma unroll
        for (int j = 0; j < 4; j++) {
            const float4 k = h4_to_f4(K[j]);
            sc[j] = q.x * k.x + q.y * k.y + q.z * k.z + q.w * k.w;
        }
#pragma unroll
        for (int j = 0; j < 4; j++) sc[j] += __shfl_xor_sync(0xffffffffu, sc[j], 1);
#pragma unroll
        for (int j = 0; j < 4; j++) sc[j] += __shfl_xor_sync(0xffffffffu, sc[j], 2);
#pragma unroll
        for (int j = 0; j < 4; j++) sc[j] = __expf(fminf(fmaxf(sc[j], -5.f), 5.f));

#pragma unroll
        for (int j = 0; j < 4; j++) {
            const float4 v = h4_to_f4(V[j]);
            av.x = fmaf(v.x, sc[j], av.x); av.y = fmaf(v.y, sc[j], av.y);
            av.z = fmaf(v.z, sc[j], av.z); av.w = fmaf(v.w, sc[j], av.w);
        }
        if ((lane & 3) == 0) z += (sc[0] + sc[1]) + (sc[2] + sc[3]);
    }
    for (; e < end; e++) {
        const int s0 = __ldg(&g_src_sorted[e]);
        const Half4 K0 = *reinterpret_cast<const Half4*>(g_Kh + (size_t)s0 * HD + lane * 4);
        const float4 k0 = h4_to_f4(K0);
        float sc0 = q.x * k0.x + q.y * k0.y + q.z * k0.z + q.w * k0.w;
        sc0 += __shfl_xor_sync(0xffffffffu, sc0, 1);
        sc0 += __shfl_xor_sync(0xffffffffu, sc0, 2);
        sc0 = __expf(fminf(fmaxf(sc0, -5.f), 5.f));
        const Half4 V0 = *reinterpret_cast<const Half4*>(g_Vh + (size_t)s0 * HD + lane * 4);
        const float4 v0 = h4_to_f4(V0);
        av.x = fmaf(v0.x, sc0, av.x); av.y = fmaf(v0.y, sc0, av.y);
        av.z = fmaf(v0.z, sc0, av.z); av.w = fmaf(v0.w, sc0, av.w);
        if ((lane & 3) == 0) z += sc0;
    }

    z = __shfl_sync(0xffffffffu, z, lane & ~3);
    const float inv = 1.f / z;

    float4 o;
    o.x = av.x * inv; o.y = av.y * inv; o.z = av.z * inv; o.w = av.w * inv;
    *reinterpret_cast<float4*>(out + (size_t)w * HD + lane * 4) = o;
}

// ---------------------------------------------------------------------------
extern "C" void kernel_launch(void* const* d_in, const int* in_sizes, int n_in,
                              void* d_out, int out_size)
{
    const float* h  = (const float*)d_in[0];
    const int* src  = (const int*)d_in[1];
    const int* dst  = (const int*)d_in[2];
    const float* Wq = (const float*)d_in[3];
    const float* Wk = (const float*)d_in[4];
    const float* Wv = (const float*)d_in[5];
    const float* bq = (const float*)d_in[6];
    const float* bk = (const float*)d_in[7];
    const float* bv = (const float*)d_in[8];
    float* out = (float*)d_out;

    const int N = in_sizes[0] / IN_DIM;
    const int E = in_sizes[1];

    // One-time setup on the uncaptured correctness call
    static cudaStream_t s2 = nullptr;
    static cudaEvent_t evFork = nullptr, evJoin = nullptr;
    static void* degptr = nullptr;
    if (s2 == nullptr) {
        cudaStreamCreateWithFlags(&s2, cudaStreamNonBlocking);
        cudaEventCreateWithFlags(&evFork, cudaEventDisableTiming);
        cudaEventCreateWithFlags(&evJoin, cudaEventDisableTiming);
        cudaGetSymbolAddress(&degptr, g_deg);
        cudaFuncSetAttribute(qkv_mma_kernel, cudaFuncAttributeMaxDynamicSharedMemorySize,
                             QKV_SMEM);
    }

    const int eb = (E + 255) / 256;
    const int nch = (N + 1023) / 1024;

    // Fork: CSR build on s2; W prepass + tensor GEMM on the main stream.
    cudaEventRecord(evFork, 0);
    cudaStreamWaitEvent(s2, evFork, 0);

    cudaMemsetAsync(degptr, 0, (size_t)N * sizeof(int), s2);
    hist_kernel<<<eb, 256, 0, s2>>>(dst, E);
    scanA_kernel<<<nch, 1024, 0, s2>>>(N);
    scanB_kernel<<<nch, 1024, 0, s2>>>(N);
    scatter_kernel<<<eb, 256, 0, s2>>>(src, dst, E);
    cudaEventRecord(evJoin, s2);

    wprep_kernel<<<(3 * 128 * 128 + 255) / 256, 256>>>(Wq, Wk, Wv);
    qkv_mma_kernel<<<(N + 127) / 128, 256, QKV_SMEM>>>(h, bq, bk, bv, N);

    // Join, then attention (warp per dst node)
    cudaStreamWaitEvent(0, evJoin, 0);
    attn_kernel<<<(N * 32 + 255) / 256, 256>>>(out, N);
}